// round 4
// baseline (speedup 1.0000x reference)
#include <cuda_runtime.h>
#include <cstdint>

// Problem constants (B=4, H=16, S=2048, D=64, fp32)
#define NBH   64          // B*H
#define SEQ   2048
#define HD    64
#define BM    64          // query rows per CTA
#define BN    64          // keys per tile
#define KST   68          // K/P smem row stride (floats) -> conflict-free frag reads
#define VST   72          // V smem row stride

__device__ __forceinline__ unsigned f2tf(float f) {
    unsigned r;
    asm("cvt.rna.tf32.f32 %0, %1;" : "=r"(r) : "f"(f));
    return r;
}

__device__ __forceinline__ void mma_tf32(float c[4], const unsigned a[4],
                                         unsigned b0, unsigned b1) {
    asm volatile(
        "mma.sync.aligned.m16n8k8.row.col.f32.tf32.tf32.f32 "
        "{%0,%1,%2,%3}, {%4,%5,%6,%7}, {%8,%9}, {%0,%1,%2,%3};"
        : "+f"(c[0]), "+f"(c[1]), "+f"(c[2]), "+f"(c[3])
        : "r"(a[0]), "r"(a[1]), "r"(a[2]), "r"(a[3]), "r"(b0), "r"(b1));
}

__global__ __launch_bounds__(128)
void flash_sdpa_tf32(const float* __restrict__ Q,
                     const float* __restrict__ K,
                     const float* __restrict__ V,
                     float* __restrict__ O) {
    // K tile (tf32 bits); after S-gemm the same region is reused to stage P.
    __shared__ __align__(16) unsigned Ks[BN * KST];
    __shared__ __align__(16) unsigned Vs[BN * VST];

    const int tid  = threadIdx.x;
    const int warp = tid >> 5;
    const int lane = tid & 31;
    const int gr   = lane >> 2;   // fragment group row   (0..7)
    const int gc   = lane & 3;    // fragment group col   (0..3)
    const int bh    = blockIdx.y;
    const int mbase = blockIdx.x * BM;

    // ---- Load this warp's Q fragments once (scaled by 1/sqrt(D)=0.125, tf32) ----
    const float* qp = Q + ((size_t)bh * SEQ + mbase + warp * 16) * HD;
    unsigned aq[8][4];
#pragma unroll
    for (int kt = 0; kt < 8; kt++) {
        aq[kt][0] = f2tf(0.125f * qp[ gr      * HD + kt * 8 + gc    ]);
        aq[kt][1] = f2tf(0.125f * qp[(gr + 8) * HD + kt * 8 + gc    ]);
        aq[kt][2] = f2tf(0.125f * qp[ gr      * HD + kt * 8 + gc + 4]);
        aq[kt][3] = f2tf(0.125f * qp[(gr + 8) * HD + kt * 8 + gc + 4]);
    }

    float o[8][4];
#pragma unroll
    for (int nt = 0; nt < 8; nt++) { o[nt][0] = 0.f; o[nt][1] = 0.f; o[nt][2] = 0.f; o[nt][3] = 0.f; }
    float m0 = -1e30f, m1 = -1e30f, l0 = 0.f, l1 = 0.f;

    const float4* kp = (const float4*)(K + (size_t)bh * SEQ * HD);
    const float4* vp = (const float4*)(V + (size_t)bh * SEQ * HD);

    for (int t = 0; t < SEQ / BN; t++) {
        __syncthreads();  // previous tile's P/V reads complete before overwrite

        // ---- Stage K,V tile (64x64 fp32 each) into smem as tf32 bits ----
#pragma unroll
        for (int i = 0; i < 8; i++) {
            int idx = tid + i * 128;          // 0..1023 float4s
            int r   = idx >> 4;               // key row within tile
            int c4  = idx & 15;               // float4 column
            float4 k4 = kp[t * (BN * HD / 4) + idx];
            float4 v4 = vp[t * (BN * HD / 4) + idx];
            uint4 ku = { f2tf(k4.x), f2tf(k4.y), f2tf(k4.z), f2tf(k4.w) };
            uint4 vu = { f2tf(v4.x), f2tf(v4.y), f2tf(v4.z), f2tf(v4.w) };
            *(uint4*)&Ks[r * KST + c4 * 4] = ku;
            *(uint4*)&Vs[r * VST + c4 * 4] = vu;
        }
        __syncthreads();

        // ---- S = (Q*scale) @ K^T : m16 x n64(keys) x k64(D) per warp ----
        float s[8][4];
#pragma unroll
        for (int nt = 0; nt < 8; nt++) { s[nt][0] = 0.f; s[nt][1] = 0.f; s[nt][2] = 0.f; s[nt][3] = 0.f; }
#pragma unroll
        for (int kt = 0; kt < 8; kt++) {
#pragma unroll
            for (int nt = 0; nt < 8; nt++) {
                unsigned b0 = Ks[(nt * 8 + gr) * KST + kt * 8 + gc    ];
                unsigned b1 = Ks[(nt * 8 + gr) * KST + kt * 8 + gc + 4];
                mma_tf32(s[nt], aq[kt], b0, b1);
            }
        }

        // ---- Online softmax (rows gr and gr+8 of this warp's 16) ----
        float mx0 = -1e30f, mx1 = -1e30f;
#pragma unroll
        for (int nt = 0; nt < 8; nt++) {
            mx0 = fmaxf(mx0, fmaxf(s[nt][0], s[nt][1]));
            mx1 = fmaxf(mx1, fmaxf(s[nt][2], s[nt][3]));
        }
        mx0 = fmaxf(mx0, __shfl_xor_sync(0xffffffffu, mx0, 1));
        mx0 = fmaxf(mx0, __shfl_xor_sync(0xffffffffu, mx0, 2));
        mx1 = fmaxf(mx1, __shfl_xor_sync(0xffffffffu, mx1, 1));
        mx1 = fmaxf(mx1, __shfl_xor_sync(0xffffffffu, mx1, 2));

        float mn0 = fmaxf(m0, mx0), mn1 = fmaxf(m1, mx1);
        float cr0 = __expf(m0 - mn0), cr1 = __expf(m1 - mn1);
        m0 = mn0; m1 = mn1;

        float ps0 = 0.f, ps1 = 0.f;
#pragma unroll
        for (int nt = 0; nt < 8; nt++) {
            s[nt][0] = __expf(s[nt][0] - mn0);
            s[nt][1] = __expf(s[nt][1] - mn0);
            s[nt][2] = __expf(s[nt][2] - mn1);
            s[nt][3] = __expf(s[nt][3] - mn1);
            ps0 += s[nt][0] + s[nt][1];
            ps1 += s[nt][2] + s[nt][3];
            o[nt][0] *= cr0; o[nt][1] *= cr0;
            o[nt][2] *= cr1; o[nt][3] *= cr1;
        }
        l0 = l0 * cr0 + ps0;
        l1 = l1 * cr1 + ps1;

        __syncthreads();  // all warps finished reading Ks; safe to overwrite with P

        // ---- Stage P (tf32) into this warp's 16-row slice of the K region ----
        unsigned* Ps = Ks + warp * 16 * KST;
#pragma unroll
        for (int nt = 0; nt < 8; nt++) {
            Ps[ gr      * KST + nt * 8 + 2 * gc    ] = f2tf(s[nt][0]);
            Ps[ gr      * KST + nt * 8 + 2 * gc + 1] = f2tf(s[nt][1]);
            Ps[(gr + 8) * KST + nt * 8 + 2 * gc    ] = f2tf(s[nt][2]);
            Ps[(gr + 8) * KST + nt * 8 + 2 * gc + 1] = f2tf(s[nt][3]);
        }
        __syncwarp();

        // ---- O += P @ V : m16 x n64(D) x k64(keys) ----
#pragma unroll
        for (int kt = 0; kt < 8; kt++) {
            unsigned pa[4];
            pa[0] = Ps[ gr      * KST + kt * 8 + gc    ];
            pa[1] = Ps[(gr + 8) * KST + kt * 8 + gc    ];
            pa[2] = Ps[ gr      * KST + kt * 8 + gc + 4];
            pa[3] = Ps[(gr + 8) * KST + kt * 8 + gc + 4];
#pragma unroll
            for (int nt = 0; nt < 8; nt++) {
                unsigned b0 = Vs[(kt * 8 + gc    ) * VST + nt * 8 + gr];
                unsigned b1 = Vs[(kt * 8 + gc + 4) * VST + nt * 8 + gr];
                mma_tf32(o[nt], pa, b0, b1);
            }
        }
    }

    // ---- Epilogue: finish row sums across the quad, normalize, store ----
    l0 += __shfl_xor_sync(0xffffffffu, l0, 1);
    l0 += __shfl_xor_sync(0xffffffffu, l0, 2);
    l1 += __shfl_xor_sync(0xffffffffu, l1, 1);
    l1 += __shfl_xor_sync(0xffffffffu, l1, 2);
    float inv0 = 1.f / l0, inv1 = 1.f / l1;

    float* op = O + ((size_t)bh * SEQ + mbase + warp * 16) * HD;
#pragma unroll
    for (int nt = 0; nt < 8; nt++) {
        *(float2*)&op[ gr      * HD + nt * 8 + 2 * gc] =
            make_float2(o[nt][0] * inv0, o[nt][1] * inv0);
        *(float2*)&op[(gr + 8) * HD + nt * 8 + 2 * gc] =
            make_float2(o[nt][2] * inv1, o[nt][3] * inv1);
    }
}

extern "C" void kernel_launch(void* const* d_in, const int* in_sizes, int n_in,
                              void* d_out, int out_size) {
    (void)in_sizes; (void)n_in; (void)out_size;
    const float* Q = (const float*)d_in[0];
    const float* K = (const float*)d_in[1];
    const float* V = (const float*)d_in[2];
    float* O = (float*)d_out;
    dim3 grid(SEQ / BM, NBH);   // 32 x 64 = 2048 CTAs
    flash_sdpa_tf32<<<grid, 128>>>(Q, K, V, O);
}

// round 6
// speedup vs baseline: 2.1726x; 2.1726x over previous
#include <cuda_runtime.h>
#include <cstdint>

// Problem constants (B=4, H=16, S=2048, D=64, fp32)
#define NBH   64          // B*H
#define SEQ   2048
#define HD    64
#define BM    128         // query rows per CTA (4 warps x two 16-row m-tiles)
#define BN    64          // keys per tile
#define QST   68          // Q smem row stride (floats): conflict-free LDSM
#define KST   68          // K smem row stride
#define VST   72          // V smem row stride: conflict-free scalar b-frag LDS

#define SMEM_WORDS (BM*QST + BN*KST + BN*VST)   // 8704 + 4352 + 4608 = 17664
#define SMEM_BYTES (SMEM_WORDS * 4)             // 70656

__device__ __forceinline__ unsigned f2tf(float f) {
    unsigned r;
    asm("cvt.rna.tf32.f32 %0, %1;" : "=r"(r) : "f"(f));
    return r;
}

__device__ __forceinline__ void mma_tf32(float c[4],
                                         unsigned a0, unsigned a1, unsigned a2, unsigned a3,
                                         unsigned b0, unsigned b1) {
    asm volatile(
        "mma.sync.aligned.m16n8k8.row.col.f32.tf32.tf32.f32 "
        "{%0,%1,%2,%3}, {%4,%5,%6,%7}, {%8,%9}, {%0,%1,%2,%3};"
        : "+f"(c[0]), "+f"(c[1]), "+f"(c[2]), "+f"(c[3])
        : "r"(a0), "r"(a1), "r"(a2), "r"(a3), "r"(b0), "r"(b1));
}

__device__ __forceinline__ void ldsm_x4(unsigned& r0, unsigned& r1, unsigned& r2, unsigned& r3,
                                        unsigned saddr) {
    asm volatile("ldmatrix.sync.aligned.m8n8.x4.shared.b16 {%0,%1,%2,%3}, [%4];"
                 : "=r"(r0), "=r"(r1), "=r"(r2), "=r"(r3) : "r"(saddr));
}

__global__ __launch_bounds__(128)
void flash_sdpa_tf32_v2(const float* __restrict__ Q,
                        const float* __restrict__ K,
                        const float* __restrict__ V,
                        float* __restrict__ O) {
    extern __shared__ unsigned smu[];
    unsigned* Qs = smu;                 // [BM][QST] tf32 bits, pre-scaled 0.125
    unsigned* Ks = Qs + BM * QST;       // [BN][KST] tf32 bits
    unsigned* Vs = Ks + BN * KST;       // [BN][VST] tf32 bits

    const int tid  = threadIdx.x;
    const int warp = tid >> 5;
    const int lane = tid & 31;
    const int gr   = lane >> 2;
    const int gc   = lane & 3;
    const int bh    = blockIdx.y;
    const int mbase = blockIdx.x * BM;

    unsigned sbase;
    {
        unsigned long long g = __cvta_generic_to_shared(smu);
        sbase = (unsigned)g;
    }
    const unsigned Qs_b = sbase;
    const unsigned Ks_b = sbase + BM * QST * 4u;
    const unsigned Vs_b = Ks_b + BN * KST * 4u;

    // ---- per-lane LDSM addressing precompute ----
    const int l8 = lane & 7;
    // Q A-frag: lanes 0-7 rows 0-7 cols0-3 | 8-15 rows 8-15 cols0-3 | 16-23 rows0-7 cols4-7 | 24-31 rows8-15 cols4-7
    const int qrow_l = warp * 32 + l8 + ((lane & 8) ? 8 : 0);
    const int qcol_l = ((lane >> 4) & 1) * 4;
    // K B-frag with key permutation kappa(n) = (n>>1) + 4*(n&1)
    const int kap    = (l8 >> 1) + ((l8 & 1) << 2);
    const int kg     = lane >> 3;                     // 0..3: (nt parity, col half)
    const int krow_l = ((kg >> 1) << 3) + kap;        // row within 16-row nt-pair span
    const int kcol_l = (kg & 1) * 4;

    // ---- stage Q once: tf32(0.125 * q) ----
    {
        const float4* qp4 = (const float4*)(Q + ((size_t)bh * SEQ + mbase) * HD);
#pragma unroll
        for (int i = 0; i < 16; i++) {
            int idx = tid + i * 128;        // 0..2047 float4s (128 rows x 16)
            int r = idx >> 4, c4 = idx & 15;
            float4 q4 = qp4[idx];
            uint4 qu = { f2tf(0.125f * q4.x), f2tf(0.125f * q4.y),
                         f2tf(0.125f * q4.z), f2tf(0.125f * q4.w) };
            *(uint4*)&Qs[r * QST + c4 * 4] = qu;
        }
    }

    float o[2][8][4];
#pragma unroll
    for (int mt = 0; mt < 2; mt++)
#pragma unroll
        for (int nt = 0; nt < 8; nt++) { o[mt][nt][0]=0.f; o[mt][nt][1]=0.f; o[mt][nt][2]=0.f; o[mt][nt][3]=0.f; }
    float mrow[2][2] = {{-1e30f,-1e30f},{-1e30f,-1e30f}};
    float lrow[2][2] = {{0.f,0.f},{0.f,0.f}};

    const float4* kp4 = (const float4*)(K + (size_t)bh * SEQ * HD);
    const float4* vp4 = (const float4*)(V + (size_t)bh * SEQ * HD);

    for (int t = 0; t < SEQ / BN; t++) {
        __syncthreads();  // prior tile's Ks/Vs reads complete (also covers Q staging at t=0)

        // ---- stage K,V tile (64x64 fp32 -> tf32 bits) ----
#pragma unroll
        for (int i = 0; i < 8; i++) {
            int idx = tid + i * 128;       // 0..1023 float4s
            int r = idx >> 4, c4 = idx & 15;
            float4 k4 = kp4[t * (BN * HD / 4) + idx];
            float4 v4 = vp4[t * (BN * HD / 4) + idx];
            uint4 ku = { f2tf(k4.x), f2tf(k4.y), f2tf(k4.z), f2tf(k4.w) };
            uint4 vu = { f2tf(v4.x), f2tf(v4.y), f2tf(v4.z), f2tf(v4.w) };
            *(uint4*)&Ks[r * KST + c4 * 4] = ku;
            *(uint4*)&Vs[r * VST + c4 * 4] = vu;
        }
        __syncthreads();

        // ---- S = (Q*scale) @ K^T with permuted key columns ----
        float s[2][8][4];
#pragma unroll
        for (int mt = 0; mt < 2; mt++)
#pragma unroll
            for (int nt = 0; nt < 8; nt++) { s[mt][nt][0]=0.f; s[mt][nt][1]=0.f; s[mt][nt][2]=0.f; s[mt][nt][3]=0.f; }

#pragma unroll
        for (int kt = 0; kt < 8; kt++) {
            unsigned kb[16];
#pragma unroll
            for (int ntp = 0; ntp < 4; ntp++) {
                unsigned addr = Ks_b + (unsigned)(((ntp * 16 + krow_l) * KST + kcol_l + kt * 8) * 4);
                ldsm_x4(kb[ntp*4+0], kb[ntp*4+1], kb[ntp*4+2], kb[ntp*4+3], addr);
            }
#pragma unroll
            for (int mt = 0; mt < 2; mt++) {
                unsigned a0, a1, a2, a3;
                unsigned qaddr = Qs_b + (unsigned)(((qrow_l + mt * 16) * QST + qcol_l + kt * 8) * 4);
                ldsm_x4(a0, a1, a2, a3, qaddr);
#pragma unroll
                for (int nt = 0; nt < 8; nt++) {
                    // kb layout: [ntp*4 + {b0(nt even), b1(nt even), b0(nt odd), b1(nt odd)}]
                    unsigned b0 = kb[(nt >> 1) * 4 + (nt & 1) * 2];
                    unsigned b1 = kb[(nt >> 1) * 4 + (nt & 1) * 2 + 1];
                    mma_tf32(s[mt][nt], a0, a1, a2, a3, b0, b1);
                }
            }
        }

        // ---- online softmax per m-tile; convert P to tf32 bits in place ----
#pragma unroll
        for (int mt = 0; mt < 2; mt++) {
            float mx0 = -1e30f, mx1 = -1e30f;
#pragma unroll
            for (int nt = 0; nt < 8; nt++) {
                mx0 = fmaxf(mx0, fmaxf(s[mt][nt][0], s[mt][nt][1]));
                mx1 = fmaxf(mx1, fmaxf(s[mt][nt][2], s[mt][nt][3]));
            }
            mx0 = fmaxf(mx0, __shfl_xor_sync(0xffffffffu, mx0, 1));
            mx0 = fmaxf(mx0, __shfl_xor_sync(0xffffffffu, mx0, 2));
            mx1 = fmaxf(mx1, __shfl_xor_sync(0xffffffffu, mx1, 1));
            mx1 = fmaxf(mx1, __shfl_xor_sync(0xffffffffu, mx1, 2));

            float mn0 = fmaxf(mrow[mt][0], mx0), mn1 = fmaxf(mrow[mt][1], mx1);
            float cr0 = __expf(mrow[mt][0] - mn0), cr1 = __expf(mrow[mt][1] - mn1);
            mrow[mt][0] = mn0; mrow[mt][1] = mn1;

            float ps0 = 0.f, ps1 = 0.f;
#pragma unroll
            for (int nt = 0; nt < 8; nt++) {
                float e0 = __expf(s[mt][nt][0] - mn0);
                float e1 = __expf(s[mt][nt][1] - mn0);
                float e2 = __expf(s[mt][nt][2] - mn1);
                float e3 = __expf(s[mt][nt][3] - mn1);
                ps0 += e0 + e1; ps1 += e2 + e3;
                s[mt][nt][0] = __uint_as_float(f2tf(e0));
                s[mt][nt][1] = __uint_as_float(f2tf(e1));
                s[mt][nt][2] = __uint_as_float(f2tf(e2));
                s[mt][nt][3] = __uint_as_float(f2tf(e3));
                o[mt][nt][0] *= cr0; o[mt][nt][1] *= cr0;
                o[mt][nt][2] *= cr1; o[mt][nt][3] *= cr1;
            }
            lrow[mt][0] = lrow[mt][0] * cr0 + ps0;
            lrow[mt][1] = lrow[mt][1] * cr1 + ps1;
        }

        // ---- O += P @ V (P A-frags = register alias of S output, thanks to kappa) ----
#pragma unroll
        for (int kt = 0; kt < 8; kt++) {
            unsigned vb[16];
#pragma unroll
            for (int nt = 0; nt < 8; nt++) {
                vb[nt*2]   = Vs[(kt * 8 + gc    ) * VST + nt * 8 + gr];
                vb[nt*2+1] = Vs[(kt * 8 + gc + 4) * VST + nt * 8 + gr];
            }
#pragma unroll
            for (int mt = 0; mt < 2; mt++) {
                unsigned a0 = __float_as_uint(s[mt][kt][0]);
                unsigned a1 = __float_as_uint(s[mt][kt][2]);
                unsigned a2 = __float_as_uint(s[mt][kt][1]);
                unsigned a3 = __float_as_uint(s[mt][kt][3]);
#pragma unroll
                for (int nt = 0; nt < 8; nt++)
                    mma_tf32(o[mt][nt], a0, a1, a2, a3, vb[nt*2], vb[nt*2+1]);
            }
        }
    }

    // ---- epilogue ----
#pragma unroll
    for (int mt = 0; mt < 2; mt++) {
        float l0 = lrow[mt][0], l1 = lrow[mt][1];
        l0 += __shfl_xor_sync(0xffffffffu, l0, 1);
        l0 += __shfl_xor_sync(0xffffffffu, l0, 2);
        l1 += __shfl_xor_sync(0xffffffffu, l1, 1);
        l1 += __shfl_xor_sync(0xffffffffu, l1, 2);
        float inv0 = 1.f / l0, inv1 = 1.f / l1;

        float* op = O + ((size_t)bh * SEQ + mbase + warp * 32 + mt * 16) * HD;
#pragma unroll
        for (int nt = 0; nt < 8; nt++) {
            *(float2*)&op[ gr      * HD + nt * 8 + 2 * gc] =
                make_float2(o[mt][nt][0] * inv0, o[mt][nt][1] * inv0);
            *(float2*)&op[(gr + 8) * HD + nt * 8 + 2 * gc] =
                make_float2(o[mt][nt][2] * inv1, o[mt][nt][3] * inv1);
        }
    }
}

extern "C" void kernel_launch(void* const* d_in, const int* in_sizes, int n_in,
                              void* d_out, int out_size) {
    (void)in_sizes; (void)n_in; (void)out_size;
    const float* Q = (const float*)d_in[0];
    const float* K = (const float*)d_in[1];
    const float* V = (const float*)d_in[2];
    float* O = (float*)d_out;
    cudaFuncSetAttribute(flash_sdpa_tf32_v2,
                         cudaFuncAttributeMaxDynamicSharedMemorySize, SMEM_BYTES);
    dim3 grid(SEQ / BM, NBH);   // 16 x 64 = 1024 CTAs
    flash_sdpa_tf32_v2<<<grid, 128, SMEM_BYTES>>>(Q, K, V, O);
}